// round 12
// baseline (speedup 1.0000x reference)
#include <cuda_runtime.h>
#include <cuda_bf16.h>
#include <math_constants.h>

// SelfContactSmall: vertices [B=2, N, 3] f32, geomask [N, N] (bool -> i32).
// out = concat(v2v_min [B*N] f32, in_contact [B*N] as 0.0/1.0 f32)
//
// v2v_min[b][j] = min over i with geomask[i][j] of ||v[b][i] - v[b][j]||^2
//
// Strategy: one thread owns 4 columns (interleaved) for BOTH batches.
// Batches are packed into f32x2 (Blackwell packed fp32) -> half the fp issues.
// Row vertices staged in SMEM as packed {b0,b1} pairs (broadcast LDS.64).
// Row dim split ISPLITS ways; partials go to a __device__ scratch array,
// a tiny second kernel reduces + thresholds. No atomics, no init kernel.

#define BATCH    2
#define THREADS  256
#define CPT      4            // columns per thread
#define ROWTILE  128
#define ISPLITS  40
#define NMAX     10475
#define THRES2   0.0004f      // 0.02^2

__device__ float g_partial[(size_t)ISPLITS * 2 * NMAX];   // ~3.35 MB scratch

// ---- f32x2 packed helpers -------------------------------------------------
__device__ __forceinline__ unsigned long long pack2(float a, float b) {
    unsigned long long r;
    asm("mov.b64 %0, {%1, %2};" : "=l"(r) : "f"(a), "f"(b));
    return r;
}
__device__ __forceinline__ void unpack2(unsigned long long v, float& a, float& b) {
    asm("mov.b64 {%0, %1}, %2;" : "=f"(a), "=f"(b) : "l"(v));
}
__device__ __forceinline__ unsigned long long add2(unsigned long long a, unsigned long long b) {
    unsigned long long r;
    asm("add.rn.f32x2 %0, %1, %2;" : "=l"(r) : "l"(a), "l"(b));
    return r;
}
__device__ __forceinline__ unsigned long long mul2(unsigned long long a, unsigned long long b) {
    unsigned long long r;
    asm("mul.rn.f32x2 %0, %1, %2;" : "=l"(r) : "l"(a), "l"(b));
    return r;
}
__device__ __forceinline__ unsigned long long fma2(unsigned long long a, unsigned long long b,
                                                   unsigned long long c) {
    unsigned long long r;
    asm("fma.rn.f32x2 %0, %1, %2, %3;" : "=l"(r) : "l"(a), "l"(b), "l"(c));
    return r;
}

// ---------------------------------------------------------------------------
// Kernel 1: masked column-min over a row split, partials to g_partial.
// grid = (ceil(N / (THREADS*CPT)), ISPLITS)
// ---------------------------------------------------------------------------
__global__ __launch_bounds__(THREADS)
void sc_min_kernel(const float* __restrict__ verts,
                   const int*   __restrict__ gmask,
                   int N) {
    __shared__ unsigned long long srow[ROWTILE][3];

    const int tid     = threadIdx.x;
    const int colbase = blockIdx.x * (THREADS * CPT);

    int  col[CPT];
    bool cv[CPT];
    unsigned long long nx[CPT], ny[CPT], nz[CPT];   // negated packed col coords

    #pragma unroll
    for (int k = 0; k < CPT; k++) {
        col[k] = colbase + k * THREADS + tid;
        cv[k]  = (col[k] < N);
        float a0 = 0.f, a1 = 0.f, a2 = 0.f, b0 = 0.f, b1 = 0.f, b2 = 0.f;
        if (cv[k]) {
            const int j = col[k];
            a0 = verts[3 * j + 0];
            a1 = verts[3 * j + 1];
            a2 = verts[3 * j + 2];
            b0 = verts[3 * (N + j) + 0];
            b1 = verts[3 * (N + j) + 1];
            b2 = verts[3 * (N + j) + 2];
        }
        nx[k] = pack2(-a0, -b0);
        ny[k] = pack2(-a1, -b1);
        nz[k] = pack2(-a2, -b2);
    }

    float m0[CPT], m1[CPT];
    #pragma unroll
    for (int k = 0; k < CPT; k++) { m0[k] = CUDART_INF_F; m1[k] = CUDART_INF_F; }

    const int chunk = (N + ISPLITS - 1) / ISPLITS;
    const int ibeg  = blockIdx.y * chunk;
    const int iend  = min(N, ibeg + chunk);

    for (int i0 = ibeg; i0 < iend; i0 += ROWTILE) {
        const int cnt = min(ROWTILE, iend - i0);

        __syncthreads();
        // Stage row vertices, batches packed into f32x2 (b0 in lo, b1 in hi).
        for (int t = tid; t < cnt * 3; t += THREADS) {
            const int r = t / 3;
            const int c = t - r * 3;
            srow[r][c] = pack2(verts[3 * (size_t)(i0 + r) + c],
                               verts[3 * (size_t)(N + i0 + r) + c]);
        }
        __syncthreads();

        const int* gm = gmask + (size_t)i0 * N;

        #pragma unroll 2
        for (int r = 0; r < cnt; r++) {
            const unsigned long long rx = srow[r][0];
            const unsigned long long ry = srow[r][1];
            const unsigned long long rz = srow[r][2];

            #pragma unroll
            for (int k = 0; k < CPT; k++) {
                const int ok = cv[k] ? gm[col[k]] : 0;

                unsigned long long dx = add2(rx, nx[k]);
                unsigned long long acc = mul2(dx, dx);
                unsigned long long dy = add2(ry, ny[k]);
                acc = fma2(dy, dy, acc);
                unsigned long long dz = add2(rz, nz[k]);
                acc = fma2(dz, dz, acc);

                float d0, d1;
                unpack2(acc, d0, d1);
                // branchless masked min (SEL + FMNMX)
                d0 = ok ? d0 : CUDART_INF_F;
                d1 = ok ? d1 : CUDART_INF_F;
                m0[k] = fminf(m0[k], d0);
                m1[k] = fminf(m1[k], d1);
            }
            gm += N;
        }
    }

    float* p = g_partial + (size_t)blockIdx.y * 2 * N;
    #pragma unroll
    for (int k = 0; k < CPT; k++) {
        if (cv[k]) {
            p[col[k]]     = m0[k];
            p[N + col[k]] = m1[k];
        }
    }
}

// ---------------------------------------------------------------------------
// Kernel 2: reduce partials over ISPLITS, write mins + contact flags.
// ---------------------------------------------------------------------------
__global__ void sc_reduce_kernel(float* __restrict__ out, int N) {
    const int idx = blockIdx.x * blockDim.x + threadIdx.x;   // over 2N
    const int n2  = 2 * N;
    if (idx < n2) {
        float m = CUDART_INF_F;
        #pragma unroll 8
        for (int s = 0; s < ISPLITS; s++)
            m = fminf(m, g_partial[(size_t)s * n2 + idx]);
        out[idx]      = m;
        out[n2 + idx] = (m < THRES2) ? 1.0f : 0.0f;
    }
}

// ---------------------------------------------------------------------------
extern "C" void kernel_launch(void* const* d_in, const int* in_sizes, int n_in,
                              void* d_out, int out_size) {
    const float* verts = (const float*)d_in[0];   // [B, N, 3] f32
    const int*   gmask = (const int*)d_in[1];     // [N, N] bool -> i32

    float* out = (float*)d_out;
    const int N = in_sizes[0] / (BATCH * 3);      // 10475

    {
        dim3 grid((N + THREADS * CPT - 1) / (THREADS * CPT), ISPLITS);
        sc_min_kernel<<<grid, THREADS>>>(verts, gmask, N);
    }
    {
        const int n2 = 2 * N;
        int blocks = (n2 + THREADS - 1) / THREADS;
        sc_reduce_kernel<<<blocks, THREADS>>>(out, N);
    }
}

// round 13
// speedup vs baseline: 1.8279x; 1.8279x over previous
#include <cuda_runtime.h>
#include <cuda_bf16.h>
#include <math_constants.h>

// SelfContactSmall: vertices [B=2, N, 3] f32, geomask [N, N] (bool -> i32).
// out = concat(v2v_min [B*N] f32, in_contact [B*N] as 0.0/1.0 f32)
//
// v2v_min[b][j] = min over i with geomask[i][j] of ||v[b][i] - v[b][j]||^2
//               = sq_j + min over masked i of (sq_i - 2*dot(v_i, v_j))
//
// Rows staged in SMEM as float4 (-2x_i, -2y_i, -2z_i, sq_i) per batch
// -> inner loop is 3 FMA + 1 predicated FMNMX per pair per batch.
// Partial mins can be negative, so atomicMin uses the order-preserving
// float->uint bit map; final kernel unmaps, adds sq_j, thresholds.

#define BATCH    2
#define THREADS  256
#define ROWTILE  128
#define ISPLITS  16
#define THRES2   0.0004f   // 0.02^2

// mapped(+inf): bits(+inf)=0x7f800000 (positive) -> ^0x80000000
#define MAPPED_INF 0xFF800000u

__device__ __forceinline__ unsigned int map_f2u(float f) {
    int b = __float_as_int(f);
    return (unsigned int)(b ^ ((b >> 31) | 0x80000000));
}
__device__ __forceinline__ float unmap_u2f(unsigned int u) {
    int b = (u & 0x80000000u) ? (int)(u ^ 0x80000000u) : ~(int)u;
    return __int_as_float(b);
}

// ---------------------------------------------------------------------------
// Kernel 1: init mapped-min region of d_out to mapped(+inf).
// ---------------------------------------------------------------------------
__global__ void sc_init_kernel(unsigned int* __restrict__ out_bits, int n_total) {
    int i = blockIdx.x * blockDim.x + threadIdx.x;
    if (i < n_total) out_bits[i] = MAPPED_INF;
}

// ---------------------------------------------------------------------------
// Kernel 2: masked column-min of (sq_i - 2*dot). One thread = one column j,
// both batches. grid.y = row splits, merged via mapped atomicMin.
// ---------------------------------------------------------------------------
__global__ __launch_bounds__(THREADS)
void sc_min_kernel(const float* __restrict__ verts,
                   const int*   __restrict__ gmask,
                   unsigned int* __restrict__ out_bits,
                   int N) {
    __shared__ float4 sv0[ROWTILE];
    __shared__ float4 sv1[ROWTILE];

    const int tid = threadIdx.x;
    const int j   = blockIdx.x * THREADS + tid;
    const bool valid = (j < N);

    const int chunk = (N + ISPLITS - 1) / ISPLITS;
    const int ibeg  = blockIdx.y * chunk;
    const int iend  = min(N, ibeg + chunk);

    // Column coords, both batches.
    float x0 = 0.f, y0 = 0.f, z0 = 0.f, x1 = 0.f, y1 = 0.f, z1 = 0.f;
    if (valid) {
        x0 = verts[3 * j + 0];
        y0 = verts[3 * j + 1];
        z0 = verts[3 * j + 2];
        x1 = verts[3 * (size_t)(N + j) + 0];
        y1 = verts[3 * (size_t)(N + j) + 1];
        z1 = verts[3 * (size_t)(N + j) + 2];
    }

    float m0 = CUDART_INF_F, m1 = CUDART_INF_F;

    for (int i0 = ibeg; i0 < iend; i0 += ROWTILE) {
        const int cnt = min(ROWTILE, iend - i0);

        __syncthreads();
        // Stage rows: float4 (-2x, -2y, -2z, sq) per batch.
        for (int t = tid; t < cnt * 2; t += THREADS) {
            const int r = t >> 1;
            const int b = t & 1;
            const float* vp = verts + 3 * (size_t)((b ? N : 0) + i0 + r);
            const float x = vp[0], y = vp[1], z = vp[2];
            const float4 v = make_float4(-2.0f * x, -2.0f * y, -2.0f * z,
                                         fmaf(z, z, fmaf(y, y, x * x)));
            if (b) sv1[r] = v; else sv0[r] = v;
        }
        __syncthreads();

        if (valid) {
            const int* gm = gmask + (size_t)i0 * N + j;
            #pragma unroll 4
            for (int r = 0; r < cnt; r++) {
                const int ok = gm[0];
                gm += N;

                const float4 a = sv0[r];
                const float d0 = fmaf(a.z, z0, fmaf(a.y, y0, fmaf(a.x, x0, a.w)));
                const float4 b = sv1[r];
                const float d1 = fmaf(b.z, z1, fmaf(b.y, y1, fmaf(b.x, x1, b.w)));

                if (ok) {
                    m0 = fminf(m0, d0);
                    m1 = fminf(m1, d1);
                }
            }
        }
    }

    if (valid) {
        atomicMin(&out_bits[j],     map_f2u(m0));
        atomicMin(&out_bits[N + j], map_f2u(m1));
    }
}

// ---------------------------------------------------------------------------
// Kernel 3: unmap, add sq_j, write mins + contact flags.
// ---------------------------------------------------------------------------
__global__ void sc_final_kernel(float* __restrict__ out,
                                const float* __restrict__ verts,
                                int n_total) {
    const int idx = blockIdx.x * blockDim.x + threadIdx.x;   // over 2N = B*N
    if (idx < n_total) {
        const float x = verts[3 * (size_t)idx + 0];
        const float y = verts[3 * (size_t)idx + 1];
        const float z = verts[3 * (size_t)idx + 2];
        const float sq = fmaf(z, z, fmaf(y, y, x * x));

        const unsigned int u = ((const unsigned int*)out)[idx];
        const float m = unmap_u2f(u) + sq;

        out[idx]           = m;
        out[n_total + idx] = (m < THRES2) ? 1.0f : 0.0f;
    }
}

// ---------------------------------------------------------------------------
extern "C" void kernel_launch(void* const* d_in, const int* in_sizes, int n_in,
                              void* d_out, int out_size) {
    const float* verts = (const float*)d_in[0];   // [B, N, 3] f32
    const int*   gmask = (const int*)d_in[1];     // [N, N] bool -> i32

    float* out = (float*)d_out;
    const int N = in_sizes[0] / (BATCH * 3);      // 10475
    const int n_total = BATCH * N;                // 20950

    {
        int blocks = (n_total + THREADS - 1) / THREADS;
        sc_init_kernel<<<blocks, THREADS>>>((unsigned int*)out, n_total);
    }
    {
        dim3 grid((N + THREADS - 1) / THREADS, ISPLITS);
        sc_min_kernel<<<grid, THREADS>>>(verts, gmask, (unsigned int*)out, N);
    }
    {
        int blocks = (n_total + THREADS - 1) / THREADS;
        sc_final_kernel<<<blocks, THREADS>>>(out, verts, n_total);
    }
}